// round 11
// baseline (speedup 1.0000x reference)
#include <cuda_runtime.h>
#include <cstdint>
#include <cstddef>

#define IN_CH  64
#define OUT_CH 128
#define TILE_M 128

// ---------------- BN scratch (no allocs allowed) ----------------
__device__ float g_sum[OUT_CH];
__device__ float g_sqsum[OUT_CH];
__device__ float g_scale[OUT_CH];
__device__ float g_bias[OUT_CH];

__global__ void zero_stats_kernel() {
    int c = threadIdx.x;
    g_sum[c]   = 0.f;
    g_sqsum[c] = 0.f;
}

__device__ __forceinline__ uint32_t cvt_tf32(float f) {
    uint32_t r;
    asm("cvt.rna.tf32.f32 %0, %1;" : "=r"(r) : "f"(f));
    return r;
}

// ---------------- mask dtype detection (bool widened to ?) ----------------
__device__ __forceinline__ int detect_mask_mode(const void* mask) {
    int w = ((const int*)mask)[0];
    if (w == 1) return 1;                       // int32
    if (__int_as_float(w) == 1.0f) return 2;    // float32
    return 0;                                   // bytes
}
__device__ __forceinline__ bool mask_at(const void* mask, int mode, long i) {
    if (mode == 1) return ((const int*)mask)[i] != 0;
    if (mode == 2) return ((const float*)mask)[i] != 0.0f;
    return ((const unsigned char*)mask)[i] != 0;
}

// smem layout (bytes)
#define A_STRIDE 68               // 64 + 4 pad
#define B_STRIDE 136              // 128 + 8 pad
#define SM_VI 0                   // int[128]
#define SM_VO 512                 // int[128]
#define SM_A  1024                // u32[128*68]
#define SM_B  (SM_A + TILE_M * A_STRIDE * 4)
#define SM_TOTAL (SM_B + IN_CH * B_STRIDE * 4)    // 70656 B

// ---------------------------------------------------------------------------
// Per block: 128 rules of ONE k (kernel arg). Gather -> tf32 mma.sync
// (M=128,N=128,K=64) -> red.global.add.v2 scatter (R6 measured-best epilogue).
// grid = (ceil(R/128), 1), block = 256 (8 warps); launched 9x (k=0..8).
// warp w: M rows [ (w>>1)*32, +32 ), N cols [ (w&1)*64, +64 )
// ---------------------------------------------------------------------------
__global__ __launch_bounds__(256) void sp_mma_kernel(
    const float* __restrict__ feats,
    const float* __restrict__ W,
    const int*   __restrict__ in_idx,
    const int*   __restrict__ out_idx,
    const void*  __restrict__ mask,
    float* __restrict__ out,
    int R, int k)
{
    extern __shared__ char smem[];
    int*      svi = (int*)(smem + SM_VI);
    int*      svo = (int*)(smem + SM_VO);
    uint32_t* sA  = (uint32_t*)(smem + SM_A);
    uint32_t* sB  = (uint32_t*)(smem + SM_B);

    const int tid  = threadIdx.x;
    const int warp = tid >> 5;
    const int lane = tid & 31;

    // ---- rule metadata (threads 0..127 handle one rule each) ----
    const int mmode = detect_mask_mode(mask);
    bool valid = false;
    if (tid < TILE_M) {
        const long r = (long)blockIdx.x * TILE_M + tid;
        int vi = 0, vo = -1;
        if (r < R) {
            const long gi = (long)k * R + r;
            valid = mask_at(mask, mmode, gi);
            if (valid) { vi = in_idx[gi]; vo = out_idx[gi]; }
        }
        svi[tid] = vi;
        svo[tid] = vo;
    }
    // valid rules are front-packed per k-row -> padded tail blocks exit whole
    if (__syncthreads_count(tid < TILE_M ? (int)valid : 0) == 0) return;

    // ---- stage B = W[k] ([64 K][128 N], tf32, padded) ----
    {
        const float* Wk = W + (size_t)k * IN_CH * OUT_CH;
        #pragma unroll
        for (int i = 0; i < (IN_CH * OUT_CH) / 256; i++) {
            int idx = tid + i * 256;
            int c = idx >> 7, n = idx & 127;
            sB[c * B_STRIDE + n] = cvt_tf32(Wk[idx]);   // coalesced
        }
    }

    // ---- gather A rows (2 threads per row, 32 floats each) ----
    {
        const int row = tid >> 1, half = tid & 1;
        const int vi = svi[row];
        const bool rv = (svo[row] >= 0);
        const float4* src = (const float4*)(feats + (size_t)vi * IN_CH) + half * 8;
        uint4* dst = (uint4*)(sA + row * A_STRIDE + half * 32);
        #pragma unroll
        for (int j = 0; j < 8; j++) {
            uint4 o = make_uint4(0u, 0u, 0u, 0u);
            if (rv) {
                float4 v = src[j];
                o.x = cvt_tf32(v.x); o.y = cvt_tf32(v.y);
                o.z = cvt_tf32(v.z); o.w = cvt_tf32(v.w);
            }
            dst[j] = o;
        }
    }
    __syncthreads();

    // ---- MMA: each warp 2 M-tiles x 8 N-tiles, 8 K-steps of k=8 ----
    const int g = lane >> 2, t = lane & 3;
    const int mbase = (warp >> 1) * 32;
    const int nbase = (warp & 1) * 64;

    float acc[2][8][4];
    #pragma unroll
    for (int mt = 0; mt < 2; mt++)
        #pragma unroll
        for (int nt = 0; nt < 8; nt++)
            #pragma unroll
            for (int j = 0; j < 4; j++) acc[mt][nt][j] = 0.f;

    #pragma unroll
    for (int ks = 0; ks < 8; ks++) {
        const int k0 = ks * 8;
        uint32_t a[2][4];
        #pragma unroll
        for (int mt = 0; mt < 2; mt++) {
            const int rg = mbase + mt * 16 + g;
            a[mt][0] = sA[(rg)     * A_STRIDE + k0 + t];
            a[mt][1] = sA[(rg + 8) * A_STRIDE + k0 + t];
            a[mt][2] = sA[(rg)     * A_STRIDE + k0 + t + 4];
            a[mt][3] = sA[(rg + 8) * A_STRIDE + k0 + t + 4];
        }
        uint32_t b[8][2];
        #pragma unroll
        for (int nt = 0; nt < 8; nt++) {
            const int n = nbase + nt * 8 + g;
            b[nt][0] = sB[(k0 + t)     * B_STRIDE + n];
            b[nt][1] = sB[(k0 + t + 4) * B_STRIDE + n];
        }
        #pragma unroll
        for (int mt = 0; mt < 2; mt++)
            #pragma unroll
            for (int nt = 0; nt < 8; nt++)
                asm("mma.sync.aligned.m16n8k8.row.col.f32.tf32.tf32.f32 "
                    "{%0,%1,%2,%3}, {%4,%5,%6,%7}, {%8,%9}, {%0,%1,%2,%3};"
                    : "+f"(acc[mt][nt][0]), "+f"(acc[mt][nt][1]),
                      "+f"(acc[mt][nt][2]), "+f"(acc[mt][nt][3])
                    : "r"(a[mt][0]), "r"(a[mt][1]), "r"(a[mt][2]), "r"(a[mt][3]),
                      "r"(b[nt][0]), "r"(b[nt][1]));
    }

    // ---- epilogue (R6 measured-best): direct red.global.add.v2 ----
    // lane t holds cols (2t, 2t+1) of rows g and g+8 per (mt, nt) tile
    #pragma unroll
    for (int mt = 0; mt < 2; mt++) {
        const int r0 = mbase + mt * 16 + g;
        const int vo0 = svo[r0];
        const int vo1 = svo[r0 + 8];
        if (vo0 >= 0) {
            float* op = out + (size_t)vo0 * OUT_CH + nbase + 2 * t;
            #pragma unroll
            for (int nt = 0; nt < 8; nt++)
                asm volatile("red.global.add.v2.f32 [%0], {%1,%2};" ::
                    "l"(op + nt * 8), "f"(acc[mt][nt][0]), "f"(acc[mt][nt][1]) : "memory");
        }
        if (vo1 >= 0) {
            float* op = out + (size_t)vo1 * OUT_CH + nbase + 2 * t;
            #pragma unroll
            for (int nt = 0; nt < 8; nt++)
                asm volatile("red.global.add.v2.f32 [%0], {%1,%2};" ::
                    "l"(op + nt * 8), "f"(acc[mt][nt][2]), "f"(acc[mt][nt][3]) : "memory");
        }
    }
}

// ---------------- BN stats / finalize / apply (R6 measured-good path) -------
__global__ void stats_kernel(const float* __restrict__ out, int n_out) {
    const int c   = threadIdx.x & (OUT_CH - 1);
    const int sub = threadIdx.x >> 7;
    const int rpb = blockDim.x >> 7;
    float s = 0.f, q = 0.f;
    for (long row = (long)blockIdx.x * rpb + sub; row < n_out;
         row += (long)gridDim.x * rpb) {
        float v = out[row * OUT_CH + c];
        s += v;
        q = fmaf(v, v, q);
    }
    atomicAdd(&g_sum[c], s);
    atomicAdd(&g_sqsum[c], q);
}

__global__ void finalize_kernel(const float* __restrict__ gamma,
                                const float* __restrict__ beta,
                                float inv_n) {
    int c = threadIdx.x;
    float mean = g_sum[c] * inv_n;
    float var  = fmaf(-mean, mean, g_sqsum[c] * inv_n);
    float sc   = gamma[c] * rsqrtf(var + 1e-5f);
    g_scale[c] = sc;
    g_bias[c]  = fmaf(-mean, sc, beta[c]);
}

__global__ void bnrelu_kernel(float* __restrict__ out, long n4) {
    long i      = (long)blockIdx.x * blockDim.x + threadIdx.x;
    long stride = (long)gridDim.x * blockDim.x;
    float4* o4  = (float4*)out;
    for (; i < n4; i += stride) {
        float4 v = o4[i];
        int c = (int)(i & 31) * 4;
        float4 sc = *(const float4*)&g_scale[c];
        float4 bi = *(const float4*)&g_bias[c];
        v.x = fmaxf(fmaf(v.x, sc.x, bi.x), 0.f);
        v.y = fmaxf(fmaf(v.y, sc.y, bi.y), 0.f);
        v.z = fmaxf(fmaf(v.z, sc.z, bi.z), 0.f);
        v.w = fmaxf(fmaf(v.w, sc.w, bi.w), 0.f);
        o4[i] = v;
    }
}

extern "C" void kernel_launch(void* const* d_in, const int* in_sizes, int n_in,
                              void* d_out, int out_size) {
    const float* feats = (const float*)d_in[0];
    const float* W     = (const float*)d_in[1];
    const float* gamma = (const float*)d_in[2];
    const float* beta  = (const float*)d_in[3];
    const int*   inI   = (const int*)d_in[4];
    const int*   outI  = (const int*)d_in[5];
    const void*  mask  = (const void*)d_in[6];
    float* out = (float*)d_out;

    const int R     = in_sizes[4] / 9;
    const int n_out = out_size / OUT_CH;

    cudaMemsetAsync(d_out, 0, (size_t)out_size * sizeof(float));
    zero_stats_kernel<<<1, OUT_CH>>>();

    cudaFuncSetAttribute(sp_mma_kernel,
                         cudaFuncAttributeMaxDynamicSharedMemorySize, SM_TOTAL);
    dim3 grid((R + TILE_M - 1) / TILE_M, 1);
    // 9 per-k launches: identical total work; places sp_mma in the ncu
    // profiled launch slot so the next round has a real profile.
    for (int k = 0; k < 9; k++)
        sp_mma_kernel<<<grid, 256, SM_TOTAL>>>(feats, W, inI, outI, mask, out, R, k);

    stats_kernel<<<1024, 512>>>(out, n_out);
    finalize_kernel<<<1, OUT_CH>>>(gamma, beta, 1.0f / (float)n_out);

    long n4 = (long)out_size / 4;
    int bgrid = (int)((n4 + 255) / 256);
    if (bgrid > 4096) bgrid = 4096;
    bnrelu_kernel<<<bgrid, 256>>>(out, n4);
}

// round 12
// speedup vs baseline: 1.2187x; 1.2187x over previous
#include <cuda_runtime.h>
#include <cstdint>
#include <cstddef>

#define IN_CH  64
#define OUT_CH 128
#define TILE_M 128
#define TILES  2                  // row-tiles per block, reusing staged B

// ---------------- BN scratch (no allocs allowed) ----------------
__device__ float g_sum[OUT_CH];
__device__ float g_sqsum[OUT_CH];
__device__ float g_scale[OUT_CH];
__device__ float g_bias[OUT_CH];

__global__ void zero_stats_kernel() {
    int c = threadIdx.x;
    g_sum[c]   = 0.f;
    g_sqsum[c] = 0.f;
}

__device__ __forceinline__ uint32_t cvt_tf32(float f) {
    uint32_t r;
    asm("cvt.rna.tf32.f32 %0, %1;" : "=r"(r) : "f"(f));
    return r;
}

// ---------------- mask dtype detection (bool widened to ?) ----------------
__device__ __forceinline__ int detect_mask_mode(const void* mask) {
    int w = ((const int*)mask)[0];
    if (w == 1) return 1;                       // int32
    if (__int_as_float(w) == 1.0f) return 2;    // float32
    return 0;                                   // bytes
}
__device__ __forceinline__ bool mask_at(const void* mask, int mode, long i) {
    if (mode == 1) return ((const int*)mask)[i] != 0;
    if (mode == 2) return ((const float*)mask)[i] != 0.0f;
    return ((const unsigned char*)mask)[i] != 0;
}

// smem layout (bytes)
#define A_STRIDE 68               // 64 + 4 pad
#define B_STRIDE 136              // 128 + 8 pad
#define SM_VI 0                   // int[128]
#define SM_VO 512                 // int[128]
#define SM_A  1024                // u32[128*68]
#define SM_B  (SM_A + TILE_M * A_STRIDE * 4)
#define SM_TOTAL (SM_B + IN_CH * B_STRIDE * 4)    // 70656 B -> 3 CTAs/SM by smem

// ---------------------------------------------------------------------------
// Per block: one k, TILES x 128 rules (B staged once). Per tile:
// gather -> tf32 mma.sync, N in 2 sequential 32-col halves (keeps live
// accumulators at 32 regs -> 3 CTAs/SM) -> red.global.add.v2 scatter.
// grid = (ceil(R/256), 9), block = 256 (8 warps)
// warp w: M rows [ (w>>1)*32, +32 ), N cols [ (w&1)*64, +64 )
// ---------------------------------------------------------------------------
__global__ __launch_bounds__(256) void sp_mma_kernel(
    const float* __restrict__ feats,
    const float* __restrict__ W,
    const int*   __restrict__ in_idx,
    const int*   __restrict__ out_idx,
    const void*  __restrict__ mask,
    float* __restrict__ out,
    int R)
{
    extern __shared__ char smem[];
    int*      svi = (int*)(smem + SM_VI);
    int*      svo = (int*)(smem + SM_VO);
    uint32_t* sA  = (uint32_t*)(smem + SM_A);
    uint32_t* sB  = (uint32_t*)(smem + SM_B);

    const int tid  = threadIdx.x;
    const int warp = tid >> 5;
    const int lane = tid & 31;
    const int k    = blockIdx.y;
    const int mmode = detect_mask_mode(mask);

    const int g = lane >> 2, t = lane & 3;
    const int mbase = (warp >> 1) * 32;
    const int nbase = (warp & 1) * 64;

    bool staged_b = false;

    for (int ti = 0; ti < TILES; ti++) {
        // ---- rule metadata for this tile (threads 0..127, one rule each) ----
        if (ti > 0) __syncthreads();           // prior scatter done before meta overwrite
        bool valid = false;
        if (tid < TILE_M) {
            const long r = (long)blockIdx.x * (TILE_M * TILES) + ti * TILE_M + tid;
            int vi = 0, vo = -1;
            if (r < R) {
                const long gi = (long)k * R + r;
                valid = mask_at(mask, mmode, gi);
                if (valid) { vi = in_idx[gi]; vo = out_idx[gi]; }
            }
            svi[tid] = vi;
            svo[tid] = vo;
        }
        // valid rules are front-packed per k-row -> empty tile => all later empty
        if (__syncthreads_count(tid < TILE_M ? (int)valid : 0) == 0) return;

        // ---- stage B = W[k] once per block ([64 K][128 N], tf32, padded) ----
        if (!staged_b) {
            const float* Wk = W + (size_t)k * IN_CH * OUT_CH;
            #pragma unroll
            for (int i = 0; i < (IN_CH * OUT_CH) / 256; i++) {
                int idx = tid + i * 256;
                int c = idx >> 7, n = idx & 127;
                sB[c * B_STRIDE + n] = cvt_tf32(Wk[idx]);   // coalesced
            }
            staged_b = true;
        }

        // ---- gather A rows (2 threads per row, 32 floats each) ----
        {
            const int row = tid >> 1, half = tid & 1;
            const int vi = svi[row];
            const bool rv = (svo[row] >= 0);
            const float4* src = (const float4*)(feats + (size_t)vi * IN_CH) + half * 8;
            uint4* dst = (uint4*)(sA + row * A_STRIDE + half * 32);
            #pragma unroll
            for (int j = 0; j < 8; j++) {
                uint4 o = make_uint4(0u, 0u, 0u, 0u);
                if (rv) {
                    float4 v = src[j];
                    o.x = cvt_tf32(v.x); o.y = cvt_tf32(v.y);
                    o.z = cvt_tf32(v.z); o.w = cvt_tf32(v.w);
                }
                dst[j] = o;
            }
        }
        __syncthreads();

        // ---- MMA in two N-halves of 32 cols (live acc = 32 regs) ----
        #pragma unroll
        for (int nh = 0; nh < 2; nh++) {
            const int nh0 = nbase + nh * 32;

            float acc[2][4][4];
            #pragma unroll
            for (int mt = 0; mt < 2; mt++)
                #pragma unroll
                for (int nt = 0; nt < 4; nt++)
                    #pragma unroll
                    for (int j = 0; j < 4; j++) acc[mt][nt][j] = 0.f;

            #pragma unroll
            for (int ks = 0; ks < 8; ks++) {
                const int k0 = ks * 8;
                uint32_t a[2][4];
                #pragma unroll
                for (int mt = 0; mt < 2; mt++) {
                    const int rg = mbase + mt * 16 + g;
                    a[mt][0] = sA[(rg)     * A_STRIDE + k0 + t];
                    a[mt][1] = sA[(rg + 8) * A_STRIDE + k0 + t];
                    a[mt][2] = sA[(rg)     * A_STRIDE + k0 + t + 4];
                    a[mt][3] = sA[(rg + 8) * A_STRIDE + k0 + t + 4];
                }
                uint32_t b[4][2];
                #pragma unroll
                for (int nt = 0; nt < 4; nt++) {
                    const int n = nh0 + nt * 8 + g;
                    b[nt][0] = sB[(k0 + t)     * B_STRIDE + n];
                    b[nt][1] = sB[(k0 + t + 4) * B_STRIDE + n];
                }
                #pragma unroll
                for (int mt = 0; mt < 2; mt++)
                    #pragma unroll
                    for (int nt = 0; nt < 4; nt++)
                        asm("mma.sync.aligned.m16n8k8.row.col.f32.tf32.tf32.f32 "
                            "{%0,%1,%2,%3}, {%4,%5,%6,%7}, {%8,%9}, {%0,%1,%2,%3};"
                            : "+f"(acc[mt][nt][0]), "+f"(acc[mt][nt][1]),
                              "+f"(acc[mt][nt][2]), "+f"(acc[mt][nt][3])
                            : "r"(a[mt][0]), "r"(a[mt][1]), "r"(a[mt][2]), "r"(a[mt][3]),
                              "r"(b[nt][0]), "r"(b[nt][1]));
            }

            // ---- scatter this half: lane t holds cols (2t,2t+1) of rows g, g+8
            #pragma unroll
            for (int mt = 0; mt < 2; mt++) {
                const int r0 = mbase + mt * 16 + g;
                const int vo0 = svo[r0];
                const int vo1 = svo[r0 + 8];
                if (vo0 >= 0) {
                    float* op = out + (size_t)vo0 * OUT_CH + nh0 + 2 * t;
                    #pragma unroll
                    for (int nt = 0; nt < 4; nt++)
                        asm volatile("red.global.add.v2.f32 [%0], {%1,%2};" ::
                            "l"(op + nt * 8), "f"(acc[mt][nt][0]), "f"(acc[mt][nt][1]) : "memory");
                }
                if (vo1 >= 0) {
                    float* op = out + (size_t)vo1 * OUT_CH + nh0 + 2 * t;
                    #pragma unroll
                    for (int nt = 0; nt < 4; nt++)
                        asm volatile("red.global.add.v2.f32 [%0], {%1,%2};" ::
                            "l"(op + nt * 8), "f"(acc[mt][nt][2]), "f"(acc[mt][nt][3]) : "memory");
                }
            }
        }
    }
}

// ---------------- BN stats / finalize / apply (measured-good path) ----------
__global__ void stats_kernel(const float* __restrict__ out, int n_out) {
    const int c   = threadIdx.x & (OUT_CH - 1);
    const int sub = threadIdx.x >> 7;
    const int rpb = blockDim.x >> 7;
    float s = 0.f, q = 0.f;
    for (long row = (long)blockIdx.x * rpb + sub; row < n_out;
         row += (long)gridDim.x * rpb) {
        float v = out[row * OUT_CH + c];
        s += v;
        q = fmaf(v, v, q);
    }
    atomicAdd(&g_sum[c], s);
    atomicAdd(&g_sqsum[c], q);
}

__global__ void finalize_kernel(const float* __restrict__ gamma,
                                const float* __restrict__ beta,
                                float inv_n) {
    int c = threadIdx.x;
    float mean = g_sum[c] * inv_n;
    float var  = fmaf(-mean, mean, g_sqsum[c] * inv_n);
    float sc   = gamma[c] * rsqrtf(var + 1e-5f);
    g_scale[c] = sc;
    g_bias[c]  = fmaf(-mean, sc, beta[c]);
}

__global__ void bnrelu_kernel(float* __restrict__ out, long n4) {
    long i      = (long)blockIdx.x * blockDim.x + threadIdx.x;
    long stride = (long)gridDim.x * blockDim.x;
    float4* o4  = (float4*)out;
    for (; i < n4; i += stride) {
        float4 v = o4[i];
        int c = (int)(i & 31) * 4;
        float4 sc = *(const float4*)&g_scale[c];
        float4 bi = *(const float4*)&g_bias[c];
        v.x = fmaxf(fmaf(v.x, sc.x, bi.x), 0.f);
        v.y = fmaxf(fmaf(v.y, sc.y, bi.y), 0.f);
        v.z = fmaxf(fmaf(v.z, sc.z, bi.z), 0.f);
        v.w = fmaxf(fmaf(v.w, sc.w, bi.w), 0.f);
        o4[i] = v;
    }
}

extern "C" void kernel_launch(void* const* d_in, const int* in_sizes, int n_in,
                              void* d_out, int out_size) {
    const float* feats = (const float*)d_in[0];
    const float* W     = (const float*)d_in[1];
    const float* gamma = (const float*)d_in[2];
    const float* beta  = (const float*)d_in[3];
    const int*   inI   = (const int*)d_in[4];
    const int*   outI  = (const int*)d_in[5];
    const void*  mask  = (const void*)d_in[6];
    float* out = (float*)d_out;

    const int R     = in_sizes[4] / 9;
    const int n_out = out_size / OUT_CH;

    cudaMemsetAsync(d_out, 0, (size_t)out_size * sizeof(float));
    zero_stats_kernel<<<1, OUT_CH>>>();

    cudaFuncSetAttribute(sp_mma_kernel,
                         cudaFuncAttributeMaxDynamicSharedMemorySize, SM_TOTAL);
    const int rows_per_blk = TILE_M * TILES;
    dim3 grid((R + rows_per_blk - 1) / rows_per_blk, 9);
    sp_mma_kernel<<<grid, 256, SM_TOTAL>>>(feats, W, inI, outI, mask, out, R);

    stats_kernel<<<1024, 512>>>(out, n_out);
    finalize_kernel<<<1, OUT_CH>>>(gamma, beta, 1.0f / (float)n_out);

    long n4 = (long)out_size / 4;
    int bgrid = (int)((n4 + 255) / 256);
    if (bgrid > 4096) bgrid = 4096;
    bnrelu_kernel<<<bgrid, 256>>>(out, n4);
}